// round 8
// baseline (speedup 1.0000x reference)
#include <cuda_runtime.h>

// Shapes (fixed): n=1024 tokens, 2L=512, H=512, H2=256.
#define NTOK 1024
#define KIN  512
#define HH   512
#define H2D  256
#define SCALE_2LOG2E 2.885390081777927f   // 2*log2(e)

// Scratch (device globals; no allocations allowed)
__device__ float g_ah[NTOK * HH];
__device__ float g_am[NTOK * HH];
__device__ float g_Ep[NTOK * H2D];  // ex2(c*A)             (head side)
__device__ float g_Eq[NTOK * H2D];  // ex2(c*(B + h2bias))  (mod side)
__device__ float g_C;               // sum(w) + outBias

// tanh(x) = 1 - 2/(exp(2x)+1); exact tails, ~1e-6 rel error.
__device__ __forceinline__ float fast_tanh(float x) {
    float e;
    asm("ex2.approx.f32 %0, %1;" : "=f"(e) : "f"(x * SCALE_2LOG2E));
    float r;
    asm("rcp.approx.f32 %0, %1;" : "=f"(r) : "f"(e + 1.0f));
    return 1.0f - 2.0f * r;
}

__device__ __forceinline__ float fast_ex2(float x) {
    float e;
    asm("ex2.approx.f32 %0, %1;" : "=f"(e) : "f"(x));
    return e;
}

// ---------------------------------------------------------------------------
// Kernel 1: [ah | am] = tanh( x @ [W_foh | W_fom] + catBias )
// 64x64 tile, BK=16, 256 threads, 4x4 micro, double-buffered smem.
// Grid (16,16) = 256 blocks.
// ---------------------------------------------------------------------------
__global__ __launch_bounds__(256)
void gemm1_tanh(const float* __restrict__ l0, const float* __restrict__ l1,
                const float* __restrict__ Wfoh, const float* __restrict__ Wfom,
                const float* __restrict__ catBias) {
    __shared__ __align__(16) float As[2][16][68];   // As[buf][k][m]
    __shared__ __align__(16) float Bs[2][16][68];   // Bs[buf][k][n]

    const int tid = threadIdx.x;
    const int n0 = blockIdx.x * 64;        // combined N (0..1023)
    const int m0 = blockIdx.y * 64;

    const bool head = (n0 < 512);
    const float* __restrict__ W = head ? Wfoh : Wfom;
    const int   wcol = head ? n0 : (n0 - 512);
    float* __restrict__ out = head ? g_ah : g_am;

    const int tx = tid & 15;
    const int ty = tid >> 4;
    const int lm  = tid >> 2;              // 0..63 (A rows)
    const int lk4 = (tid & 3) * 4;         // 0,4,8,12
    const int lk  = tid >> 4;              // 0..15 (B k)
    const int ln  = (tid & 15) * 4;        // 0..60 (B n)

    // prologue load k0 = 0
    float4 av = *(const float4*)(l0 + (size_t)(m0 + lm) * 256 + lk4);
    float4 bv = *(const float4*)(W + (size_t)lk * HH + wcol + ln);
    As[0][lk4 + 0][lm] = av.x;
    As[0][lk4 + 1][lm] = av.y;
    As[0][lk4 + 2][lm] = av.z;
    As[0][lk4 + 3][lm] = av.w;
    *(float4*)&Bs[0][lk][ln] = bv;
    __syncthreads();

    float acc[4][4] = {};
    int cur = 0;

    for (int k0 = 0; k0 < KIN; k0 += 16) {
        float4 av2, bv2;
        const int kn = k0 + 16;
        if (kn < KIN) {
            const float* __restrict__ xsrc =
                (kn < 256) ? (l0 + (size_t)(m0 + lm) * 256 + (kn + lk4))
                           : (l1 + (size_t)(m0 + lm) * 256 + (kn - 256 + lk4));
            av2 = *(const float4*)xsrc;
            bv2 = *(const float4*)(W + (size_t)(kn + lk) * HH + wcol + ln);
        }

#pragma unroll
        for (int kk = 0; kk < 16; kk++) {
            float4 a4 = *(const float4*)&As[cur][kk][ty * 4];
            float4 b4 = *(const float4*)&Bs[cur][kk][tx * 4];
            float aa[4] = {a4.x, a4.y, a4.z, a4.w};
            float bb[4] = {b4.x, b4.y, b4.z, b4.w};
#pragma unroll
            for (int i = 0; i < 4; i++)
#pragma unroll
                for (int j = 0; j < 4; j++)
                    acc[i][j] = fmaf(aa[i], bb[j], acc[i][j]);
        }

        if (kn < KIN) {
            const int nxt = cur ^ 1;
            As[nxt][lk4 + 0][lm] = av2.x;
            As[nxt][lk4 + 1][lm] = av2.y;
            As[nxt][lk4 + 2][lm] = av2.z;
            As[nxt][lk4 + 3][lm] = av2.w;
            *(float4*)&Bs[nxt][lk][ln] = bv2;
            __syncthreads();
            cur = nxt;
        }
    }

    const float4 bias4 = *(const float4*)&catBias[n0 + tx * 4];
#pragma unroll
    for (int i = 0; i < 4; i++) {
        float4 v;
        v.x = fast_tanh(acc[i][0] + bias4.x);
        v.y = fast_tanh(acc[i][1] + bias4.y);
        v.z = fast_tanh(acc[i][2] + bias4.z);
        v.w = fast_tanh(acc[i][3] + bias4.w);
        *(float4*)&out[(size_t)(m0 + ty * 4 + i) * HH + wcol + tx * 4] = v;
    }
}

// ---------------------------------------------------------------------------
// Kernel 2: Ep = ex2( c * (ah @ hid2Layer[0:512]) )
//           Eq = ex2( c * (am @ hid2Layer[512:1024] + hid2Bias) )
// 64x64 tile, BK=16, 256 threads, 4x4 micro, double-buffered.
// Grid (8,16) = 128 blocks.
// ---------------------------------------------------------------------------
__global__ __launch_bounds__(256)
void gemm2_exp(const float* __restrict__ h2L, const float* __restrict__ h2B) {
    __shared__ __align__(16) float As[2][16][68];
    __shared__ __align__(16) float Bs[2][16][68];

    const int tid = threadIdx.x;
    const int n0 = blockIdx.x * 64;        // combined N (0..511)
    const int m0 = blockIdx.y * 64;

    const bool isP = (n0 < 256);
    const float* __restrict__ Asrc = isP ? g_ah : g_am;
    const int   wrow = isP ? 0 : 512;
    const int   col0 = isP ? n0 : (n0 - 256);
    float* __restrict__ out = isP ? g_Ep : g_Eq;

    const int tx = tid & 15;
    const int ty = tid >> 4;
    const int lm  = tid >> 2;
    const int lk4 = (tid & 3) * 4;
    const int lk  = tid >> 4;
    const int ln  = (tid & 15) * 4;

    float4 av = *(const float4*)(Asrc + (size_t)(m0 + lm) * HH + lk4);
    float4 bv = *(const float4*)(h2L + (size_t)(wrow + lk) * H2D + col0 + ln);
    As[0][lk4 + 0][lm] = av.x;
    As[0][lk4 + 1][lm] = av.y;
    As[0][lk4 + 2][lm] = av.z;
    As[0][lk4 + 3][lm] = av.w;
    *(float4*)&Bs[0][lk][ln] = bv;
    __syncthreads();

    float acc[4][4] = {};
    int cur = 0;

    for (int k0 = 0; k0 < HH; k0 += 16) {
        float4 av2, bv2;
        const int kn = k0 + 16;
        if (kn < HH) {
            av2 = *(const float4*)(Asrc + (size_t)(m0 + lm) * HH + kn + lk4);
            bv2 = *(const float4*)(h2L + (size_t)(wrow + kn + lk) * H2D + col0 + ln);
        }

#pragma unroll
        for (int kk = 0; kk < 16; kk++) {
            float4 a4 = *(const float4*)&As[cur][kk][ty * 4];
            float4 b4 = *(const float4*)&Bs[cur][kk][tx * 4];
            float aa[4] = {a4.x, a4.y, a4.z, a4.w};
            float bb[4] = {b4.x, b4.y, b4.z, b4.w};
#pragma unroll
            for (int i = 0; i < 4; i++)
#pragma unroll
                for (int j = 0; j < 4; j++)
                    acc[i][j] = fmaf(aa[i], bb[j], acc[i][j]);
        }

        if (kn < HH) {
            const int nxt = cur ^ 1;
            As[nxt][lk4 + 0][lm] = av2.x;
            As[nxt][lk4 + 1][lm] = av2.y;
            As[nxt][lk4 + 2][lm] = av2.z;
            As[nxt][lk4 + 3][lm] = av2.w;
            *(float4*)&Bs[nxt][lk][ln] = bv2;
            __syncthreads();
            cur = nxt;
        }
    }

#pragma unroll
    for (int j = 0; j < 4; j++) {
        const float bias = isP ? 0.0f : h2B[col0 + tx * 4 + j];
#pragma unroll
        for (int i = 0; i < 4; i++) {
            float v = fast_ex2((acc[i][j] + bias) * SCALE_2LOG2E);
            out[(size_t)(m0 + ty * 4 + i) * H2D + col0 + tx * 4 + j] = v;
        }
    }
}

// ---------------------------------------------------------------------------
// Kernel 3: g_C = sum(outLayer) + outBias
// ---------------------------------------------------------------------------
__global__ void sumw_kernel(const float* __restrict__ outL,
                            const float* __restrict__ outB) {
    __shared__ float s[256];
    s[threadIdx.x] = outL[threadIdx.x];
    __syncthreads();
    for (int o = 128; o > 0; o >>= 1) {
        if (threadIdx.x < o) s[threadIdx.x] += s[threadIdx.x + o];
        __syncthreads();
    }
    if (threadIdx.x == 0) g_C = s[0] + outB[0];
}

// ---------------------------------------------------------------------------
// Kernel 4: pairwise scores (1 MUFU + 2 FMA per element):
//   scores[i,j] = C + sum_h (-2*w_h) * rcp( Ep[i,h]*Eq[j,h] + 1 )
// Persistent grid of 740 = 148 SMs x 5 CTAs; each block strides over the
// 1024 32x32 (i,j) tiles. Thread covers rows {ti, ti+16} x cols {tj, tj+16}
// -> Eq LDS lane stride = 132 floats (bank step 4) -> conflict-free LDS.128.
// ---------------------------------------------------------------------------
__device__ __forceinline__ float pterm(float ep, float eq, float w, float acc) {
    float t = fmaf(ep, eq, 1.0f);
    float r;
    asm("rcp.approx.f32 %0, %1;" : "=f"(r) : "f"(t));
    return fmaf(w, r, acc);
}

#define NTILES 1024

__global__ __launch_bounds__(256, 5)
void pairwise_kernel(const float* __restrict__ outL, float* __restrict__ out) {
    __shared__ __align__(16) float Eps[32][132];
    __shared__ __align__(16) float Eqs[32][132];
    __shared__ __align__(16) float ws[256];

    const int tid = threadIdx.x;
    ws[tid] = -2.0f * outL[tid];
    const float C = g_C;

    const int tj = tid & 15;
    const int ti = tid >> 4;

    for (int t = blockIdx.x; t < NTILES; t += gridDim.x) {
        const int i0 = (t >> 5) * 32;
        const int j0 = (t & 31) * 32;

        float acc00 = 0.f, acc01 = 0.f, acc10 = 0.f, acc11 = 0.f;

#pragma unroll
        for (int ph = 0; ph < 2; ph++) {
            __syncthreads();   // prior reads done (and ws visible on 1st pass)
#pragma unroll
            for (int p = 0; p < 4; p++) {
                int lin = tid + p * 256;
                int row = lin >> 5;            // 0..31
                int c   = (lin & 31) * 4;      // 0..124
                *(float4*)&Eps[row][c] =
                    *(const float4*)&g_Ep[(size_t)(i0 + row) * H2D + ph * 128 + c];
                *(float4*)&Eqs[row][c] =
                    *(const float4*)&g_Eq[(size_t)(j0 + row) * H2D + ph * 128 + c];
            }
            __syncthreads();

            const float* __restrict__ p0 = &Eps[ti][0];
            const float* __restrict__ p1 = &Eps[ti + 16][0];
            const float* __restrict__ q0 = &Eqs[tj][0];
            const float* __restrict__ q1 = &Eqs[tj + 16][0];
            const float* __restrict__ pw = &ws[ph * 128];

#pragma unroll 8
            for (int h4 = 0; h4 < 32; h4++) {
                float4 a0 = *(const float4*)(p0 + h4 * 4);
                float4 a1 = *(const float4*)(p1 + h4 * 4);
                float4 b0 = *(const float4*)(q0 + h4 * 4);
                float4 b1 = *(const float4*)(q1 + h4 * 4);
                float4 w4 = *(const float4*)(pw + h4 * 4);

                acc00 = pterm(a0.x, b0.x, w4.x, acc00);
                acc01 = pterm(a0.x, b1.x, w4.x, acc01);
                acc10 = pterm(a1.x, b0.x, w4.x, acc10);
                acc11 = pterm(a1.x, b1.x, w4.x, acc11);

                acc00 = pterm(a0.y, b0.y, w4.y, acc00);
                acc01 = pterm(a0.y, b1.y, w4.y, acc01);
                acc10 = pterm(a1.y, b0.y, w4.y, acc10);
                acc11 = pterm(a1.y, b1.y, w4.y, acc11);

                acc00 = pterm(a0.z, b0.z, w4.z, acc00);
                acc01 = pterm(a0.z, b1.z, w4.z, acc01);
                acc10 = pterm(a1.z, b0.z, w4.z, acc10);
                acc11 = pterm(a1.z, b1.z, w4.z, acc11);

                acc00 = pterm(a0.w, b0.w, w4.w, acc00);
                acc01 = pterm(a0.w, b1.w, w4.w, acc01);
                acc10 = pterm(a1.w, b0.w, w4.w, acc10);
                acc11 = pterm(a1.w, b1.w, w4.w, acc11);
            }
        }

        const int i = i0 + ti;
        const int j = j0 + tj;
        out[(size_t)i * NTOK + j]             = C + acc00;
        out[(size_t)i * NTOK + j + 16]        = C + acc01;
        out[(size_t)(i + 16) * NTOK + j]      = C + acc10;
        out[(size_t)(i + 16) * NTOK + j + 16] = C + acc11;
    }
}

// ---------------------------------------------------------------------------
extern "C" void kernel_launch(void* const* d_in, const int* in_sizes, int n_in,
                              void* d_out, int out_size) {
    const float* l0   = (const float*)d_in[0];   // lstms0 [1024,256]
    const float* l1   = (const float*)d_in[1];   // lstms1 [1024,256]
    const float* Wfoh = (const float*)d_in[2];   // [512,512]
    const float* Wfom = (const float*)d_in[3];   // [512,512]
    const float* catB = (const float*)d_in[4];   // [1,1024]
    const float* h2L  = (const float*)d_in[5];   // [1024,256]
    const float* h2B  = (const float*)d_in[6];   // [1,256]
    const float* outL = (const float*)d_in[7];   // [256,1]
    const float* outB = (const float*)d_in[8];   // [1,1]
    float* out = (float*)d_out;                  // [1024,1024]

    gemm1_tanh<<<dim3(16, 16), 256>>>(l0, l1, Wfoh, Wfom, catB);
    gemm2_exp<<<dim3(8, 16), 256>>>(h2L, h2B);
    sumw_kernel<<<1, 256>>>(outL, outB);
    pairwise_kernel<<<740, 256>>>(outL, out);
}

// round 9
// speedup vs baseline: 1.1698x; 1.1698x over previous
#include <cuda_runtime.h>

// Shapes (fixed): n=1024 tokens, 2L=512, H=512, H2=256.
#define NTOK 1024
#define KIN  512
#define HH   512
#define H2D  256
#define SCALE_2LOG2E 2.885390081777927f   // 2*log2(e)

// Scratch (device globals; no allocations allowed)
__device__ float g_ah[NTOK * HH];
__device__ float g_am[NTOK * HH];
__device__ float g_Ep[NTOK * H2D];  // ex2(c*A)             (head side)
__device__ float g_Eq[NTOK * H2D];  // ex2(c*(B + h2bias))  (mod side)
__device__ float g_C;               // sum(w) + outBias

// tanh(x) = 1 - 2/(exp(2x)+1); exact tails, ~1e-6 rel error.
__device__ __forceinline__ float fast_tanh(float x) {
    float e;
    asm("ex2.approx.f32 %0, %1;" : "=f"(e) : "f"(x * SCALE_2LOG2E));
    float r;
    asm("rcp.approx.f32 %0, %1;" : "=f"(r) : "f"(e + 1.0f));
    return 1.0f - 2.0f * r;
}

__device__ __forceinline__ float fast_ex2(float x) {
    float e;
    asm("ex2.approx.f32 %0, %1;" : "=f"(e) : "f"(x));
    return e;
}

// ---------------------------------------------------------------------------
// Kernel 1: [ah | am] = tanh( x @ [W_foh | W_fom] + catBias )
// 64x64 tile, BK=16, 256 threads, 4x4 micro, double-buffered smem.
// Grid (16,16) = 256 blocks.
// ---------------------------------------------------------------------------
__global__ __launch_bounds__(256)
void gemm1_tanh(const float* __restrict__ l0, const float* __restrict__ l1,
                const float* __restrict__ Wfoh, const float* __restrict__ Wfom,
                const float* __restrict__ catBias) {
    __shared__ __align__(16) float As[2][16][68];   // As[buf][k][m]
    __shared__ __align__(16) float Bs[2][16][68];   // Bs[buf][k][n]

    const int tid = threadIdx.x;
    const int n0 = blockIdx.x * 64;        // combined N (0..1023)
    const int m0 = blockIdx.y * 64;

    const bool head = (n0 < 512);
    const float* __restrict__ W = head ? Wfoh : Wfom;
    const int   wcol = head ? n0 : (n0 - 512);
    float* __restrict__ out = head ? g_ah : g_am;

    const int tx = tid & 15;
    const int ty = tid >> 4;
    const int lm  = tid >> 2;              // 0..63 (A rows)
    const int lk4 = (tid & 3) * 4;         // 0,4,8,12
    const int lk  = tid >> 4;              // 0..15 (B k)
    const int ln  = (tid & 15) * 4;        // 0..60 (B n)

    // prologue load k0 = 0
    float4 av = *(const float4*)(l0 + (size_t)(m0 + lm) * 256 + lk4);
    float4 bv = *(const float4*)(W + (size_t)lk * HH + wcol + ln);
    As[0][lk4 + 0][lm] = av.x;
    As[0][lk4 + 1][lm] = av.y;
    As[0][lk4 + 2][lm] = av.z;
    As[0][lk4 + 3][lm] = av.w;
    *(float4*)&Bs[0][lk][ln] = bv;
    __syncthreads();

    float acc[4][4] = {};
    int cur = 0;

    for (int k0 = 0; k0 < KIN; k0 += 16) {
        float4 av2, bv2;
        const int kn = k0 + 16;
        if (kn < KIN) {
            const float* __restrict__ xsrc =
                (kn < 256) ? (l0 + (size_t)(m0 + lm) * 256 + (kn + lk4))
                           : (l1 + (size_t)(m0 + lm) * 256 + (kn - 256 + lk4));
            av2 = *(const float4*)xsrc;
            bv2 = *(const float4*)(W + (size_t)(kn + lk) * HH + wcol + ln);
        }

#pragma unroll
        for (int kk = 0; kk < 16; kk++) {
            float4 a4 = *(const float4*)&As[cur][kk][ty * 4];
            float4 b4 = *(const float4*)&Bs[cur][kk][tx * 4];
            float aa[4] = {a4.x, a4.y, a4.z, a4.w};
            float bb[4] = {b4.x, b4.y, b4.z, b4.w};
#pragma unroll
            for (int i = 0; i < 4; i++)
#pragma unroll
                for (int j = 0; j < 4; j++)
                    acc[i][j] = fmaf(aa[i], bb[j], acc[i][j]);
        }

        if (kn < KIN) {
            const int nxt = cur ^ 1;
            As[nxt][lk4 + 0][lm] = av2.x;
            As[nxt][lk4 + 1][lm] = av2.y;
            As[nxt][lk4 + 2][lm] = av2.z;
            As[nxt][lk4 + 3][lm] = av2.w;
            *(float4*)&Bs[nxt][lk][ln] = bv2;
            __syncthreads();
            cur = nxt;
        }
    }

    const float4 bias4 = *(const float4*)&catBias[n0 + tx * 4];
#pragma unroll
    for (int i = 0; i < 4; i++) {
        float4 v;
        v.x = fast_tanh(acc[i][0] + bias4.x);
        v.y = fast_tanh(acc[i][1] + bias4.y);
        v.z = fast_tanh(acc[i][2] + bias4.z);
        v.w = fast_tanh(acc[i][3] + bias4.w);
        *(float4*)&out[(size_t)(m0 + ty * 4 + i) * HH + wcol + tx * 4] = v;
    }
}

// ---------------------------------------------------------------------------
// Kernel 2: Ep = ex2( c * (ah @ hid2Layer[0:512]) )
//           Eq = ex2( c * (am @ hid2Layer[512:1024] + hid2Bias) )
// 64x64 tile, BK=16, 256 threads, 4x4 micro, double-buffered.
// Grid (8,16) = 128 blocks.
// ---------------------------------------------------------------------------
__global__ __launch_bounds__(256)
void gemm2_exp(const float* __restrict__ h2L, const float* __restrict__ h2B) {
    __shared__ __align__(16) float As[2][16][68];
    __shared__ __align__(16) float Bs[2][16][68];

    const int tid = threadIdx.x;
    const int n0 = blockIdx.x * 64;        // combined N (0..511)
    const int m0 = blockIdx.y * 64;

    const bool isP = (n0 < 256);
    const float* __restrict__ Asrc = isP ? g_ah : g_am;
    const int   wrow = isP ? 0 : 512;
    const int   col0 = isP ? n0 : (n0 - 256);
    float* __restrict__ out = isP ? g_Ep : g_Eq;

    const int tx = tid & 15;
    const int ty = tid >> 4;
    const int lm  = tid >> 2;
    const int lk4 = (tid & 3) * 4;
    const int lk  = tid >> 4;
    const int ln  = (tid & 15) * 4;

    float4 av = *(const float4*)(Asrc + (size_t)(m0 + lm) * HH + lk4);
    float4 bv = *(const float4*)(h2L + (size_t)(wrow + lk) * H2D + col0 + ln);
    As[0][lk4 + 0][lm] = av.x;
    As[0][lk4 + 1][lm] = av.y;
    As[0][lk4 + 2][lm] = av.z;
    As[0][lk4 + 3][lm] = av.w;
    *(float4*)&Bs[0][lk][ln] = bv;
    __syncthreads();

    float acc[4][4] = {};
    int cur = 0;

    for (int k0 = 0; k0 < HH; k0 += 16) {
        float4 av2, bv2;
        const int kn = k0 + 16;
        if (kn < HH) {
            av2 = *(const float4*)(Asrc + (size_t)(m0 + lm) * HH + kn + lk4);
            bv2 = *(const float4*)(h2L + (size_t)(wrow + kn + lk) * H2D + col0 + ln);
        }

#pragma unroll
        for (int kk = 0; kk < 16; kk++) {
            float4 a4 = *(const float4*)&As[cur][kk][ty * 4];
            float4 b4 = *(const float4*)&Bs[cur][kk][tx * 4];
            float aa[4] = {a4.x, a4.y, a4.z, a4.w};
            float bb[4] = {b4.x, b4.y, b4.z, b4.w};
#pragma unroll
            for (int i = 0; i < 4; i++)
#pragma unroll
                for (int j = 0; j < 4; j++)
                    acc[i][j] = fmaf(aa[i], bb[j], acc[i][j]);
        }

        if (kn < HH) {
            const int nxt = cur ^ 1;
            As[nxt][lk4 + 0][lm] = av2.x;
            As[nxt][lk4 + 1][lm] = av2.y;
            As[nxt][lk4 + 2][lm] = av2.z;
            As[nxt][lk4 + 3][lm] = av2.w;
            *(float4*)&Bs[nxt][lk][ln] = bv2;
            __syncthreads();
            cur = nxt;
        }
    }

#pragma unroll
    for (int j = 0; j < 4; j++) {
        const float bias = isP ? 0.0f : h2B[col0 + tx * 4 + j];
#pragma unroll
        for (int i = 0; i < 4; i++) {
            float v = fast_ex2((acc[i][j] + bias) * SCALE_2LOG2E);
            out[(size_t)(m0 + ty * 4 + i) * H2D + col0 + tx * 4 + j] = v;
        }
    }
}

// ---------------------------------------------------------------------------
// Kernel 3: g_C = sum(outLayer) + outBias
// ---------------------------------------------------------------------------
__global__ void sumw_kernel(const float* __restrict__ outL,
                            const float* __restrict__ outB) {
    __shared__ float s[256];
    s[threadIdx.x] = outL[threadIdx.x];
    __syncthreads();
    for (int o = 128; o > 0; o >>= 1) {
        if (threadIdx.x < o) s[threadIdx.x] += s[threadIdx.x + o];
        __syncthreads();
    }
    if (threadIdx.x == 0) g_C = s[0] + outB[0];
}

// ---------------------------------------------------------------------------
// Kernel 4: pairwise scores (1 MUFU + 2 FMA per element):
//   scores[i,j] = C + sum_h (-2*w_h) * rcp( Ep[i,h]*Eq[j,h] + 1 )
// 64x64 output tile per block, 256 threads, 4x4 micro-tile per thread
// (rows ty+16r, cols tx+16c). h processed in 4 chunks of 64.
// Grid 256 blocks = one wave. Per h4 step: 64 MUFU vs 9 LDS.128 (Ep/w
// broadcast; Eq conflict-free via 68-float row padding).
// ---------------------------------------------------------------------------
__device__ __forceinline__ float pterm(float ep, float eq, float w, float acc) {
    float t = fmaf(ep, eq, 1.0f);
    float r;
    asm("rcp.approx.f32 %0, %1;" : "=f"(r) : "f"(t));
    return fmaf(w, r, acc);
}

__global__ __launch_bounds__(256, 2)
void pairwise_kernel(const float* __restrict__ outL, float* __restrict__ out) {
    __shared__ __align__(16) float Eps[64][68];
    __shared__ __align__(16) float Eqs[64][68];
    __shared__ __align__(16) float ws[256];

    const int tid = threadIdx.x;
    ws[tid] = -2.0f * outL[tid];

    const int j0 = (blockIdx.x & 15) * 64;
    const int i0 = (blockIdx.x >> 4) * 64;

    const int tx = tid & 15;
    const int ty = tid >> 4;

    float acc[4][4] = {};

    for (int ch = 0; ch < 4; ch++) {
        __syncthreads();   // ws visible (ch=0) / prior chunk reads done
#pragma unroll
        for (int p = 0; p < 4; p++) {
            int lin = tid + p * 256;
            int row = lin >> 4;            // 0..63
            int c   = (lin & 15) * 4;      // 0..60
            *(float4*)&Eps[row][c] =
                *(const float4*)&g_Ep[(size_t)(i0 + row) * H2D + ch * 64 + c];
            *(float4*)&Eqs[row][c] =
                *(const float4*)&g_Eq[(size_t)(j0 + row) * H2D + ch * 64 + c];
        }
        __syncthreads();

        const float* __restrict__ pw = &ws[ch * 64];
#pragma unroll 2
        for (int h4 = 0; h4 < 16; h4++) {
            float4 a[4], b[4];
#pragma unroll
            for (int r = 0; r < 4; r++)
                a[r] = *(const float4*)&Eps[ty + 16 * r][h4 * 4];
#pragma unroll
            for (int c = 0; c < 4; c++)
                b[c] = *(const float4*)&Eqs[tx + 16 * c][h4 * 4];
            float4 w4 = *(const float4*)(pw + h4 * 4);

#pragma unroll
            for (int r = 0; r < 4; r++) {
#pragma unroll
                for (int c = 0; c < 4; c++) {
                    acc[r][c] = pterm(a[r].x, b[c].x, w4.x, acc[r][c]);
                    acc[r][c] = pterm(a[r].y, b[c].y, w4.y, acc[r][c]);
                    acc[r][c] = pterm(a[r].z, b[c].z, w4.z, acc[r][c]);
                    acc[r][c] = pterm(a[r].w, b[c].w, w4.w, acc[r][c]);
                }
            }
        }
    }

    const float C = g_C;
#pragma unroll
    for (int r = 0; r < 4; r++)
#pragma unroll
        for (int c = 0; c < 4; c++)
            out[(size_t)(i0 + ty + 16 * r) * NTOK + (j0 + tx + 16 * c)]
                = C + acc[r][c];
}

// ---------------------------------------------------------------------------
extern "C" void kernel_launch(void* const* d_in, const int* in_sizes, int n_in,
                              void* d_out, int out_size) {
    const float* l0   = (const float*)d_in[0];   // lstms0 [1024,256]
    const float* l1   = (const float*)d_in[1];   // lstms1 [1024,256]
    const float* Wfoh = (const float*)d_in[2];   // [512,512]
    const float* Wfom = (const float*)d_in[3];   // [512,512]
    const float* catB = (const float*)d_in[4];   // [1,1024]
    const float* h2L  = (const float*)d_in[5];   // [1024,256]
    const float* h2B  = (const float*)d_in[6];   // [1,256]
    const float* outL = (const float*)d_in[7];   // [256,1]
    const float* outB = (const float*)d_in[8];   // [1,1]
    float* out = (float*)d_out;                  // [1024,1024]

    gemm1_tanh<<<dim3(16, 16), 256>>>(l0, l1, Wfoh, Wfom, catB);
    gemm2_exp<<<dim3(8, 16), 256>>>(h2L, h2B);
    sumw_kernel<<<1, 256>>>(outL, outB);
    pairwise_kernel<<<256, 256>>>(outL, out);
}

// round 10
// speedup vs baseline: 1.1759x; 1.0052x over previous
#include <cuda_runtime.h>

// Shapes (fixed): n=1024 tokens, 2L=512, H=512, H2=256.
#define NTOK 1024
#define KIN  512
#define HH   512
#define H2D  256
#define SCALE_2LOG2E 2.885390081777927f   // 2*log2(e)

// Scratch (device globals; no allocations allowed)
__device__ float g_ah[NTOK * HH];
__device__ float g_am[NTOK * HH];
__device__ float g_Ep[NTOK * H2D];  // ex2(c*A)             (head side)
__device__ float g_Eq[NTOK * H2D];  // ex2(c*(B + h2bias))  (mod side)
__device__ float g_C;               // sum(w) + outBias

// tanh(x) = 1 - 2/(exp(2x)+1); exact tails, ~1e-6 rel error.
__device__ __forceinline__ float fast_tanh(float x) {
    float e;
    asm("ex2.approx.f32 %0, %1;" : "=f"(e) : "f"(x * SCALE_2LOG2E));
    float r;
    asm("rcp.approx.f32 %0, %1;" : "=f"(r) : "f"(e + 1.0f));
    return 1.0f - 2.0f * r;
}

__device__ __forceinline__ float fast_ex2(float x) {
    float e;
    asm("ex2.approx.f32 %0, %1;" : "=f"(e) : "f"(x));
    return e;
}

// ---------------------------------------------------------------------------
// Kernel 1: [ah | am] = tanh( x @ [W_foh | W_fom] + catBias )
// 64x64 tile, BK=16, 256 threads, 4x4 micro, double-buffered smem.
// Grid (16,16) = 256 blocks.
// ---------------------------------------------------------------------------
__global__ __launch_bounds__(256)
void gemm1_tanh(const float* __restrict__ l0, const float* __restrict__ l1,
                const float* __restrict__ Wfoh, const float* __restrict__ Wfom,
                const float* __restrict__ catBias) {
    __shared__ __align__(16) float As[2][16][68];   // As[buf][k][m]
    __shared__ __align__(16) float Bs[2][16][68];   // Bs[buf][k][n]

    const int tid = threadIdx.x;
    const int n0 = blockIdx.x * 64;        // combined N (0..1023)
    const int m0 = blockIdx.y * 64;

    const bool head = (n0 < 512);
    const float* __restrict__ W = head ? Wfoh : Wfom;
    const int   wcol = head ? n0 : (n0 - 512);
    float* __restrict__ out = head ? g_ah : g_am;

    const int tx = tid & 15;
    const int ty = tid >> 4;
    const int lm  = tid >> 2;              // 0..63 (A rows)
    const int lk4 = (tid & 3) * 4;         // 0,4,8,12
    const int lk  = tid >> 4;              // 0..15 (B k)
    const int ln  = (tid & 15) * 4;        // 0..60 (B n)

    // prologue load k0 = 0
    float4 av = *(const float4*)(l0 + (size_t)(m0 + lm) * 256 + lk4);
    float4 bv = *(const float4*)(W + (size_t)lk * HH + wcol + ln);
    As[0][lk4 + 0][lm] = av.x;
    As[0][lk4 + 1][lm] = av.y;
    As[0][lk4 + 2][lm] = av.z;
    As[0][lk4 + 3][lm] = av.w;
    *(float4*)&Bs[0][lk][ln] = bv;
    __syncthreads();

    float acc[4][4] = {};
    int cur = 0;

    for (int k0 = 0; k0 < KIN; k0 += 16) {
        float4 av2, bv2;
        const int kn = k0 + 16;
        if (kn < KIN) {
            const float* __restrict__ xsrc =
                (kn < 256) ? (l0 + (size_t)(m0 + lm) * 256 + (kn + lk4))
                           : (l1 + (size_t)(m0 + lm) * 256 + (kn - 256 + lk4));
            av2 = *(const float4*)xsrc;
            bv2 = *(const float4*)(W + (size_t)(kn + lk) * HH + wcol + ln);
        }

#pragma unroll
        for (int kk = 0; kk < 16; kk++) {
            float4 a4 = *(const float4*)&As[cur][kk][ty * 4];
            float4 b4 = *(const float4*)&Bs[cur][kk][tx * 4];
            float aa[4] = {a4.x, a4.y, a4.z, a4.w};
            float bb[4] = {b4.x, b4.y, b4.z, b4.w};
#pragma unroll
            for (int i = 0; i < 4; i++)
#pragma unroll
                for (int j = 0; j < 4; j++)
                    acc[i][j] = fmaf(aa[i], bb[j], acc[i][j]);
        }

        if (kn < KIN) {
            const int nxt = cur ^ 1;
            As[nxt][lk4 + 0][lm] = av2.x;
            As[nxt][lk4 + 1][lm] = av2.y;
            As[nxt][lk4 + 2][lm] = av2.z;
            As[nxt][lk4 + 3][lm] = av2.w;
            *(float4*)&Bs[nxt][lk][ln] = bv2;
            __syncthreads();
            cur = nxt;
        }
    }

    const float4 bias4 = *(const float4*)&catBias[n0 + tx * 4];
#pragma unroll
    for (int i = 0; i < 4; i++) {
        float4 v;
        v.x = fast_tanh(acc[i][0] + bias4.x);
        v.y = fast_tanh(acc[i][1] + bias4.y);
        v.z = fast_tanh(acc[i][2] + bias4.z);
        v.w = fast_tanh(acc[i][3] + bias4.w);
        *(float4*)&out[(size_t)(m0 + ty * 4 + i) * HH + wcol + tx * 4] = v;
    }
}

// ---------------------------------------------------------------------------
// Kernel 2: Ep = ex2( c * (ah @ hid2Layer[0:512]) )
//           Eq = ex2( c * (am @ hid2Layer[512:1024] + hid2Bias) )
// 64x64 tile, BK=16, 256 threads, 4x4 micro, double-buffered.
// Grid (8,16) = 128 blocks.
// ---------------------------------------------------------------------------
__global__ __launch_bounds__(256)
void gemm2_exp(const float* __restrict__ h2L, const float* __restrict__ h2B) {
    __shared__ __align__(16) float As[2][16][68];
    __shared__ __align__(16) float Bs[2][16][68];

    const int tid = threadIdx.x;
    const int n0 = blockIdx.x * 64;        // combined N (0..511)
    const int m0 = blockIdx.y * 64;

    const bool isP = (n0 < 256);
    const float* __restrict__ Asrc = isP ? g_ah : g_am;
    const int   wrow = isP ? 0 : 512;
    const int   col0 = isP ? n0 : (n0 - 256);
    float* __restrict__ out = isP ? g_Ep : g_Eq;

    const int tx = tid & 15;
    const int ty = tid >> 4;
    const int lm  = tid >> 2;
    const int lk4 = (tid & 3) * 4;
    const int lk  = tid >> 4;
    const int ln  = (tid & 15) * 4;

    float4 av = *(const float4*)(Asrc + (size_t)(m0 + lm) * HH + lk4);
    float4 bv = *(const float4*)(h2L + (size_t)(wrow + lk) * H2D + col0 + ln);
    As[0][lk4 + 0][lm] = av.x;
    As[0][lk4 + 1][lm] = av.y;
    As[0][lk4 + 2][lm] = av.z;
    As[0][lk4 + 3][lm] = av.w;
    *(float4*)&Bs[0][lk][ln] = bv;
    __syncthreads();

    float acc[4][4] = {};
    int cur = 0;

    for (int k0 = 0; k0 < HH; k0 += 16) {
        float4 av2, bv2;
        const int kn = k0 + 16;
        if (kn < HH) {
            av2 = *(const float4*)(Asrc + (size_t)(m0 + lm) * HH + kn + lk4);
            bv2 = *(const float4*)(h2L + (size_t)(wrow + kn + lk) * H2D + col0 + ln);
        }

#pragma unroll
        for (int kk = 0; kk < 16; kk++) {
            float4 a4 = *(const float4*)&As[cur][kk][ty * 4];
            float4 b4 = *(const float4*)&Bs[cur][kk][tx * 4];
            float aa[4] = {a4.x, a4.y, a4.z, a4.w};
            float bb[4] = {b4.x, b4.y, b4.z, b4.w};
#pragma unroll
            for (int i = 0; i < 4; i++)
#pragma unroll
                for (int j = 0; j < 4; j++)
                    acc[i][j] = fmaf(aa[i], bb[j], acc[i][j]);
        }

        if (kn < HH) {
            const int nxt = cur ^ 1;
            As[nxt][lk4 + 0][lm] = av2.x;
            As[nxt][lk4 + 1][lm] = av2.y;
            As[nxt][lk4 + 2][lm] = av2.z;
            As[nxt][lk4 + 3][lm] = av2.w;
            *(float4*)&Bs[nxt][lk][ln] = bv2;
            __syncthreads();
            cur = nxt;
        }
    }

#pragma unroll
    for (int j = 0; j < 4; j++) {
        const float bias = isP ? 0.0f : h2B[col0 + tx * 4 + j];
#pragma unroll
        for (int i = 0; i < 4; i++) {
            float v = fast_ex2((acc[i][j] + bias) * SCALE_2LOG2E);
            out[(size_t)(m0 + ty * 4 + i) * H2D + col0 + tx * 4 + j] = v;
        }
    }
}

// ---------------------------------------------------------------------------
// Kernel 3: g_C = sum(outLayer) + outBias
// ---------------------------------------------------------------------------
__global__ void sumw_kernel(const float* __restrict__ outL,
                            const float* __restrict__ outB) {
    __shared__ float s[256];
    s[threadIdx.x] = outL[threadIdx.x];
    __syncthreads();
    for (int o = 128; o > 0; o >>= 1) {
        if (threadIdx.x < o) s[threadIdx.x] += s[threadIdx.x + o];
        __syncthreads();
    }
    if (threadIdx.x == 0) g_C = s[0] + outB[0];
}

// ---------------------------------------------------------------------------
// Kernel 4: pairwise scores (1 MUFU + 2 FMA per element):
//   scores[i,j] = C + sum_h (-2*w_h) * rcp( Ep[i,h]*Eq[j,h] + 1 )
// 64x64 output tile per block, 256 threads, 4x4 micro-tile per thread
// (rows ty+16r, cols tx+16c). h processed in 4 chunks of 64.
// Grid 256 blocks = one wave. Per h4 step: 64 MUFU vs 9 LDS.128 (Ep/w
// broadcast; Eq conflict-free via 68-float row padding).
// ---------------------------------------------------------------------------
__device__ __forceinline__ float pterm(float ep, float eq, float w, float acc) {
    float t = fmaf(ep, eq, 1.0f);
    float r;
    asm("rcp.approx.f32 %0, %1;" : "=f"(r) : "f"(t));
    return fmaf(w, r, acc);
}

__global__ __launch_bounds__(256, 2)
void pairwise_kernel(const float* __restrict__ outL, float* __restrict__ out) {
    __shared__ __align__(16) float Eps[64][68];
    __shared__ __align__(16) float Eqs[64][68];
    __shared__ __align__(16) float ws[256];

    const int tid = threadIdx.x;
    ws[tid] = -2.0f * outL[tid];

    const int j0 = (blockIdx.x & 15) * 64;
    const int i0 = (blockIdx.x >> 4) * 64;

    const int tx = tid & 15;
    const int ty = tid >> 4;

    float acc[4][4] = {};

    for (int ch = 0; ch < 4; ch++) {
        __syncthreads();   // ws visible (ch=0) / prior chunk reads done
#pragma unroll
        for (int p = 0; p < 4; p++) {
            int lin = tid + p * 256;
            int row = lin >> 4;            // 0..63
            int c   = (lin & 15) * 4;      // 0..60
            *(float4*)&Eps[row][c] =
                *(const float4*)&g_Ep[(size_t)(i0 + row) * H2D + ch * 64 + c];
            *(float4*)&Eqs[row][c] =
                *(const float4*)&g_Eq[(size_t)(j0 + row) * H2D + ch * 64 + c];
        }
        __syncthreads();

        const float* __restrict__ pw = &ws[ch * 64];
#pragma unroll 2
        for (int h4 = 0; h4 < 16; h4++) {
            float4 a[4], b[4];
#pragma unroll
            for (int r = 0; r < 4; r++)
                a[r] = *(const float4*)&Eps[ty + 16 * r][h4 * 4];
#pragma unroll
            for (int c = 0; c < 4; c++)
                b[c] = *(const float4*)&Eqs[tx + 16 * c][h4 * 4];
            float4 w4 = *(const float4*)(pw + h4 * 4);

#pragma unroll
            for (int r = 0; r < 4; r++) {
#pragma unroll
                for (int c = 0; c < 4; c++) {
                    acc[r][c] = pterm(a[r].x, b[c].x, w4.x, acc[r][c]);
                    acc[r][c] = pterm(a[r].y, b[c].y, w4.y, acc[r][c]);
                    acc[r][c] = pterm(a[r].z, b[c].z, w4.z, acc[r][c]);
                    acc[r][c] = pterm(a[r].w, b[c].w, w4.w, acc[r][c]);
                }
            }
        }
    }

    const float C = g_C;
#pragma unroll
    for (int r = 0; r < 4; r++)
#pragma unroll
        for (int c = 0; c < 4; c++)
            out[(size_t)(i0 + ty + 16 * r) * NTOK + (j0 + tx + 16 * c)]
                = C + acc[r][c];
}

// ---------------------------------------------------------------------------
extern "C" void kernel_launch(void* const* d_in, const int* in_sizes, int n_in,
                              void* d_out, int out_size) {
    const float* l0   = (const float*)d_in[0];   // lstms0 [1024,256]
    const float* l1   = (const float*)d_in[1];   // lstms1 [1024,256]
    const float* Wfoh = (const float*)d_in[2];   // [512,512]
    const float* Wfom = (const float*)d_in[3];   // [512,512]
    const float* catB = (const float*)d_in[4];   // [1,1024]
    const float* h2L  = (const float*)d_in[5];   // [1024,256]
    const float* h2B  = (const float*)d_in[6];   // [1,256]
    const float* outL = (const float*)d_in[7];   // [256,1]
    const float* outB = (const float*)d_in[8];   // [1,1]
    float* out = (float*)d_out;                  // [1024,1024]

    gemm1_tanh<<<dim3(16, 16), 256>>>(l0, l1, Wfoh, Wfom, catB);
    gemm2_exp<<<dim3(8, 16), 256>>>(h2L, h2B);
    sumw_kernel<<<1, 256>>>(outL, outB);
    pairwise_kernel<<<256, 256>>>(outL, out);
}